// round 15
// baseline (speedup 1.0000x reference)
#include <cuda_runtime.h>
#include <cuda_fp16.h>
#include <math.h>
#include <stdint.h>

// Problem constants
#define BATCH 8
#define SEQ   2048
#define DIM   768
#define MROWS (BATCH * SEQ)   // 16384

// GEMM tiling: CTA 128x128, 4 warps (2x2), warp tile 64x64  (R7 config, frozen)
#define BM 128
#define BN 128
#define BKH 32                 // k-chunk in halves
#define STAGES 3
#define ROWB 80                // smem bytes per row: 64B data + 16B pad
#define TILEB (128 * ROWB)     // 10240 B per operand tile
#define STAGEB (2 * TILEB)
#define SMEM_BYTES (STAGES * STAGEB)   // 61440  (x2 CTAs = 120KB <= 227KB)

// ---------------------------------------------------------------------------
// Scratch (allocation-free contract: __device__ globals)
// ---------------------------------------------------------------------------
__device__ __half g_xh  [(size_t)MROWS * DIM];
__device__ __half g_Wqh [DIM * DIM];
__device__ __half g_Wkh [DIM * DIM];
__device__ __half g_Wph [DIM * DIM];
__device__ __half g_WvTh[DIM * DIM];                  // Wv transposed, fp16
__device__ __half g_Mh  [DIM * DIM];                  // M = Wp @ Wv, fp16
__device__ float  g_bvp [DIM];                        // bvp = Wp·bv + bp
__device__ __half g_Qh  [(size_t)MROWS * DIM];
__device__ __half g_Kh  [(size_t)MROWS * DIM];
__device__ __half g_Vpth[(size_t)BATCH * DIM * SEQ];  // Vp^T: [b][f][s]
__device__ __half g_Ah  [(size_t)BATCH * SEQ * SEQ];  // attention matrix

// ---------------------------------------------------------------------------
// Helpers
// ---------------------------------------------------------------------------
__device__ __forceinline__ uint32_t smem_u32(const void* p) {
    uint32_t a;
    asm("{ .reg .u64 t; cvta.to.shared.u64 t, %1; cvt.u32.u64 %0, t; }" : "=r"(a) : "l"(p));
    return a;
}

__device__ __forceinline__ void cpasync16(uint32_t dst, const void* src) {
    asm volatile("cp.async.cg.shared.global [%0], [%1], 16;" :: "r"(dst), "l"(src) : "memory");
}

__device__ __forceinline__ void ldm_x4(uint32_t* r, uint32_t addr) {
    asm volatile("ldmatrix.sync.aligned.m8n8.x4.shared.b16 {%0,%1,%2,%3}, [%4];"
                 : "=r"(r[0]), "=r"(r[1]), "=r"(r[2]), "=r"(r[3]) : "r"(addr));
}

__device__ __forceinline__ void mma_f16(float* d, const uint32_t* a, const uint32_t* b) {
    asm volatile(
        "mma.sync.aligned.m16n8k16.row.col.f32.f16.f16.f32 "
        "{%0,%1,%2,%3}, {%4,%5,%6,%7}, {%8,%9}, {%0,%1,%2,%3};"
        : "+f"(d[0]), "+f"(d[1]), "+f"(d[2]), "+f"(d[3])
        : "r"(a[0]), "r"(a[1]), "r"(a[2]), "r"(a[3]), "r"(b[0]), "r"(b[1]));
}

// ---------------------------------------------------------------------------
// fp32 -> fp16 converters
// ---------------------------------------------------------------------------
__global__ void __launch_bounds__(256) cvt_f2h(const float* __restrict__ in,
                                               __half* __restrict__ out, int n8)
{
    for (int i = blockIdx.x * blockDim.x + threadIdx.x; i < n8; i += gridDim.x * blockDim.x) {
        float4 v0 = reinterpret_cast<const float4*>(in)[2 * i];
        float4 v1 = reinterpret_cast<const float4*>(in)[2 * i + 1];
        uint4 o;
        __half2 h;
        h = __floats2half2_rn(v0.x, v0.y); o.x = *reinterpret_cast<uint32_t*>(&h);
        h = __floats2half2_rn(v0.z, v0.w); o.y = *reinterpret_cast<uint32_t*>(&h);
        h = __floats2half2_rn(v1.x, v1.y); o.z = *reinterpret_cast<uint32_t*>(&h);
        h = __floats2half2_rn(v1.z, v1.w); o.w = *reinterpret_cast<uint32_t*>(&h);
        reinterpret_cast<uint4*>(out)[i] = o;
    }
}

// 3 weights (Wq, Wk, Wp) in one launch: blockIdx.y selects the matrix.
__global__ void __launch_bounds__(256) cvt_weights(
    const float* __restrict__ w0, const float* __restrict__ w1,
    const float* __restrict__ w2,
    __half* __restrict__ o0, __half* __restrict__ o1,
    __half* __restrict__ o2, int n8)
{
    const float* in  = (blockIdx.y == 0) ? w0 : (blockIdx.y == 1) ? w1 : w2;
    __half*      out = (blockIdx.y == 0) ? o0 : (blockIdx.y == 1) ? o1 : o2;
    for (int i = blockIdx.x * blockDim.x + threadIdx.x; i < n8; i += gridDim.x * blockDim.x) {
        float4 v0 = reinterpret_cast<const float4*>(in)[2 * i];
        float4 v1 = reinterpret_cast<const float4*>(in)[2 * i + 1];
        uint4 o;
        __half2 h;
        h = __floats2half2_rn(v0.x, v0.y); o.x = *reinterpret_cast<uint32_t*>(&h);
        h = __floats2half2_rn(v0.z, v0.w); o.y = *reinterpret_cast<uint32_t*>(&h);
        h = __floats2half2_rn(v1.x, v1.y); o.z = *reinterpret_cast<uint32_t*>(&h);
        h = __floats2half2_rn(v1.z, v1.w); o.w = *reinterpret_cast<uint32_t*>(&h);
        reinterpret_cast<uint4*>(out)[i] = o;
    }
}

// Transpose-convert: WvT[d,k] = (half)Wv[k,d]. 32x32 smem tiles.
__global__ void __launch_bounds__(256) cvt_transpose(const float* __restrict__ in,
                                                     __half* __restrict__ out)
{
    __shared__ float tile[32][33];
    const int bx = blockIdx.x * 32;   // k base
    const int by = blockIdx.y * 32;   // d base
    const int tx = threadIdx.x & 31;
    const int ty = threadIdx.x >> 5;  // 0..7
    #pragma unroll
    for (int i = 0; i < 4; i++) {
        int k = bx + ty + i * 8;
        tile[ty + i * 8][tx] = in[(size_t)k * DIM + by + tx];
    }
    __syncthreads();
    #pragma unroll
    for (int i = 0; i < 4; i++) {
        int d = by + ty + i * 8;
        out[(size_t)d * DIM + bx + tx] = __float2half_rn(tile[tx][ty + i * 8]);
    }
}

// bvp[f] = bp[f] + sum_k Wp[f,k] * bv[k]
__global__ void __launch_bounds__(128) bvp_kernel(const float* __restrict__ Wp,
                                                  const float* __restrict__ bv,
                                                  const float* __restrict__ bp,
                                                  float* __restrict__ bvp)
{
    const int f = blockIdx.x * 128 + threadIdx.x;
    float s = bp[f];
    const float* row = Wp + (size_t)f * DIM;
    for (int k = 0; k < DIM; k++) s += row[k] * bv[k];
    bvp[f] = s;
}

// ===========================================================================
// Shared mainloop (R7 config, frozen): 128x128 CTA tile of A @ B^T into acc.
// ===========================================================================
__device__ __forceinline__ void hgemm_mainloop(
    const __half* __restrict__ Ab, const __half* __restrict__ Bb,
    int K, uint32_t sbase, int tid, int lane, int warpM, int warpN,
    float acc[4][8][4])
{
    const int r0 = tid >> 2;       // 0..31
    const int kc = tid & 3;        // 0..3

    const int nc = K / BKH;

    auto prefetch = [&](int c) {
        const int s = c % STAGES;
        if (c < nc) {
            const __half* ap = Ab + (size_t)r0 * K + c * BKH + kc * 8;
            const __half* bp = Bb + (size_t)r0 * K + c * BKH + kc * 8;
            const uint32_t da = sbase + s * STAGEB + r0 * ROWB + kc * 16;
            const uint32_t db = da + TILEB;
            #pragma unroll
            for (int rr = 0; rr < 4; rr++) {
                cpasync16(da + rr * 32 * ROWB, ap + (size_t)(rr * 32) * K);
                cpasync16(db + rr * 32 * ROWB, bp + (size_t)(rr * 32) * K);
            }
        }
        asm volatile("cp.async.commit_group;" ::: "memory");
    };

    prefetch(0);
    prefetch(1);

    for (int c = 0; c < nc; c++) {
        asm volatile("cp.async.wait_group %0;" :: "n"(STAGES - 2) : "memory");
        __syncthreads();

        const int s = c % STAGES;
        const uint32_t sa = sbase + s * STAGEB;
        const uint32_t sb = sa + TILEB;

        #pragma unroll
        for (int kt = 0; kt < 2; kt++) {
            uint32_t af[4][4], bf[8][2];
            #pragma unroll
            for (int mt = 0; mt < 4; mt++) {
                const int m = warpM * 64 + mt * 16 + (lane & 15);
                const int k = kt * 16 + 8 * (lane >> 4);
                ldm_x4(af[mt], sa + m * ROWB + k * 2);
            }
            #pragma unroll
            for (int nb = 0; nb < 4; nb++) {
                const int n = warpN * 64 + nb * 16 + (lane & 7) + 8 * (lane >> 4);
                const int k = kt * 16 + 8 * ((lane >> 3) & 1);
                uint32_t r[4];
                ldm_x4(r, sb + n * ROWB + k * 2);
                bf[nb * 2][0]     = r[0]; bf[nb * 2][1]     = r[1];
                bf[nb * 2 + 1][0] = r[2]; bf[nb * 2 + 1][1] = r[3];
            }
            #pragma unroll
            for (int mt = 0; mt < 4; mt++)
                #pragma unroll
                for (int nt = 0; nt < 8; nt++)
                    mma_f16(acc[mt][nt], af[mt], bf[nt]);
        }
        prefetch(c + 2);
    }
    asm volatile("cp.async.wait_group 0;" ::: "memory");
}

// ---------------------------------------------------------------------------
// Merged Q/K/Vp projection: grid (6, 128, 3); z selects weight/output.
// z<2 -> Qh/Kh row-major (+bias); z=2 -> Vp = x@M^T, transposed Vpt store
// (NO bias: folded into bvp).
// ---------------------------------------------------------------------------
__global__ void __launch_bounds__(128, 2) hgemm_qkv(
    const __half* __restrict__ xh,
    const __half* __restrict__ Wq, const __half* __restrict__ Wk, const __half* __restrict__ M,
    const float* __restrict__ bq, const float* __restrict__ bk,
    __half* __restrict__ Qh, __half* __restrict__ Kh, __half* __restrict__ Vpth)
{
    extern __shared__ __align__(16) char smem[];
    const uint32_t sbase = smem_u32(smem);
    const int tid  = threadIdx.x;
    const int lane = tid & 31;
    const int wid  = tid >> 5;
    const int warpM = wid & 1;
    const int warpN = wid >> 1;
    const int bx = blockIdx.x, by = blockIdx.y, bz = blockIdx.z;

    const __half* W    = (bz == 0) ? Wq : (bz == 1) ? Wk : M;
    const float*  bias = (bz == 0) ? bq : (bz == 1) ? bk : nullptr;

    const __half* Ab = xh + (size_t)(by * BM) * DIM;
    const __half* Bb = W  + (size_t)(bx * BN) * DIM;

    float acc[4][8][4];
    #pragma unroll
    for (int i = 0; i < 4; i++)
        #pragma unroll
        for (int j = 0; j < 8; j++)
            #pragma unroll
            for (int q = 0; q < 4; q++) acc[i][j][q] = 0.0f;

    hgemm_mainloop(Ab, Bb, DIM, sbase, tid, lane, warpM, warpN, acc);

    const int rbase = lane >> 2;
    const int cbase = 2 * (lane & 3);

    if (bz < 2) {
        __half* Cb = (bz == 0 ? Qh : Kh) + (size_t)(by * BM) * DIM + bx * BN;
        #pragma unroll
        for (int mt = 0; mt < 4; mt++) {
            #pragma unroll
            for (int nt = 0; nt < 8; nt++) {
                const int col = warpN * 64 + nt * 8 + cbase;
                const float b0 = bias[bx * BN + col];
                const float b1 = bias[bx * BN + col + 1];
                #pragma unroll
                for (int h = 0; h < 2; h++) {
                    const int row = warpM * 64 + mt * 16 + rbase + 8 * h;
                    *reinterpret_cast<__half2*>(Cb + (size_t)row * DIM + col) =
                        __floats2half2_rn(acc[mt][nt][2 * h + 0] + b0,
                                          acc[mt][nt][2 * h + 1] + b1);
                }
            }
        }
    } else {
        // transposed store into Vpt[b][f][s] via smem staging (no bias)
        __syncthreads();
        __half* Ts = reinterpret_cast<__half*>(smem);   // [128 f][136 m-halves]
        #pragma unroll
        for (int mt = 0; mt < 4; mt++) {
            #pragma unroll
            for (int nt = 0; nt < 8; nt++) {
                const int col = warpN * 64 + nt * 8 + cbase;
                #pragma unroll
                for (int h = 0; h < 2; h++) {
                    const int row = warpM * 64 + mt * 16 + rbase + 8 * h;
                    Ts[(col)     * 136 + row] = __float2half_rn(acc[mt][nt][2 * h + 0]);
                    Ts[(col + 1) * 136 + row] = __float2half_rn(acc[mt][nt][2 * h + 1]);
                }
            }
        }
        __syncthreads();
        const int mglob = by * BM;
        const int bb = mglob / SEQ;
        const int s0 = mglob % SEQ;
        __half* Ob = Vpth + ((size_t)bb * DIM + bx * BN) * SEQ + s0;
        const int d = tid;
        const uint4* src = reinterpret_cast<const uint4*>(Ts + d * 136);
        uint4* dst = reinterpret_cast<uint4*>(Ob + (size_t)d * SEQ);
        #pragma unroll
        for (int i = 0; i < 16; i++) dst[i] = src[i];
    }
}

// ---------------------------------------------------------------------------
// General GEMM (R7): OUTMODE 0 fp16 row-major; OUTMODE 2 fp32 row-major.
// ---------------------------------------------------------------------------
template<int OUTMODE>
__global__ void __launch_bounds__(128, 2) hgemm_kernel(
    const __half* __restrict__ A, const __half* __restrict__ B,
    const float* __restrict__ bias, void* __restrict__ Cv,
    int ldC, int K, float scale,
    size_t strideA, size_t strideB, size_t strideC)
{
    extern __shared__ __align__(16) char smem[];
    const uint32_t sbase = smem_u32(smem);
    const int tid  = threadIdx.x;
    const int lane = tid & 31;
    const int wid  = tid >> 5;
    const int warpM = wid & 1;
    const int warpN = wid >> 1;
    const int bx = blockIdx.x, by = blockIdx.y, bz = blockIdx.z;

    const __half* Ab = A + bz * strideA + (size_t)(by * BM) * K;
    const __half* Bb = B + bz * strideB + (size_t)(bx * BN) * K;

    float acc[4][8][4];
    #pragma unroll
    for (int i = 0; i < 4; i++)
        #pragma unroll
        for (int j = 0; j < 8; j++)
            #pragma unroll
            for (int q = 0; q < 4; q++) acc[i][j][q] = 0.0f;

    hgemm_mainloop(Ab, Bb, K, sbase, tid, lane, warpM, warpN, acc);

    const int rbase = lane >> 2;
    const int cbase = 2 * (lane & 3);

    #pragma unroll
    for (int mt = 0; mt < 4; mt++) {
        #pragma unroll
        for (int nt = 0; nt < 8; nt++) {
            const int col = warpN * 64 + nt * 8 + cbase;
            const float b0 = bias ? bias[bx * BN + col]     : 0.0f;
            const float b1 = bias ? bias[bx * BN + col + 1] : 0.0f;
            #pragma unroll
            for (int h = 0; h < 2; h++) {
                const int row = warpM * 64 + mt * 16 + rbase + 8 * h;
                const float v0 = acc[mt][nt][2 * h + 0] * scale + b0;
                const float v1 = acc[mt][nt][2 * h + 1] * scale + b1;
                if (OUTMODE == 0) {
                    __half* Cb = (__half*)Cv + bz * strideC + (size_t)(by * BM) * ldC + bx * BN;
                    *reinterpret_cast<__half2*>(Cb + (size_t)row * ldC + col) =
                        __floats2half2_rn(v0, v1);
                } else {
                    float* Cb = (float*)Cv + bz * strideC + (size_t)(by * BM) * ldC + bx * BN;
                    *reinterpret_cast<float2*>(Cb + (size_t)row * ldC + col) =
                        make_float2(v0, v1);
                }
            }
        }
    }
}

// ---------------------------------------------------------------------------
// Row softmax over SEQ=2048 fp16 elements: one block (256 threads) per row.
// ---------------------------------------------------------------------------
__global__ void __launch_bounds__(256) softmax_h(__half* __restrict__ alpha)
{
    __shared__ float redmax[8];
    __shared__ float redsum[8];

    __half* row = alpha + (size_t)blockIdx.x * SEQ;
    const int tid = threadIdx.x;

    uint4 u = reinterpret_cast<uint4*>(row)[tid];     // 8 halves
    __half2* hp = reinterpret_cast<__half2*>(&u);
    float v[8];
    #pragma unroll
    for (int i = 0; i < 4; i++) {
        float2 f = __half22float2(hp[i]);
        v[2 * i] = f.x; v[2 * i + 1] = f.y;
    }

    float m = v[0];
    #pragma unroll
    for (int i = 1; i < 8; i++) m = fmaxf(m, v[i]);
    #pragma unroll
    for (int o = 16; o > 0; o >>= 1) m = fmaxf(m, __shfl_xor_sync(0xffffffffu, m, o));
    if ((tid & 31) == 0) redmax[tid >> 5] = m;
    __syncthreads();
    if (tid < 32) {
        float t = (tid < 8) ? redmax[tid] : -INFINITY;
        #pragma unroll
        for (int o = 4; o > 0; o >>= 1) t = fmaxf(t, __shfl_xor_sync(0xffffffffu, t, o));
        if (tid == 0) redmax[0] = t;
    }
    __syncthreads();
    m = redmax[0];

    float s = 0.0f;
    #pragma unroll
    for (int i = 0; i < 8; i++) { v[i] = __expf(v[i] - m); s += v[i]; }
    #pragma unroll
    for (int o = 16; o > 0; o >>= 1) s += __shfl_xor_sync(0xffffffffu, s, o);
    if ((tid & 31) == 0) redsum[tid >> 5] = s;
    __syncthreads();
    if (tid < 32) {
        float t = (tid < 8) ? redsum[tid] : 0.0f;
        #pragma unroll
        for (int o = 4; o > 0; o >>= 1) t += __shfl_xor_sync(0xffffffffu, t, o);
        if (tid == 0) redsum[0] = t;
    }
    __syncthreads();
    const float inv = 1.0f / redsum[0];

    #pragma unroll
    for (int i = 0; i < 4; i++)
        hp[i] = __floats2half2_rn(v[2 * i] * inv, v[2 * i + 1] * inv);
    reinterpret_cast<uint4*>(row)[tid] = u;
}

// ---------------------------------------------------------------------------
// kernel_launch
// ---------------------------------------------------------------------------
extern "C" void kernel_launch(void* const* d_in, const int* in_sizes, int n_in,
                              void* d_out, int out_size)
{
    (void)in_sizes; (void)n_in; (void)out_size;

    const float* x  = (const float*)d_in[0];
    const float* Wq = (const float*)d_in[1];
    const float* bq = (const float*)d_in[2];
    const float* Wk = (const float*)d_in[3];
    const float* bk = (const float*)d_in[4];
    const float* Wv = (const float*)d_in[5];
    const float* bv = (const float*)d_in[6];
    const float* Wp = (const float*)d_in[7];
    const float* bp = (const float*)d_in[8];
    float* out = (float*)d_out;

    __half *xh, *Wqh, *Wkh, *Wph, *WvTh, *Mh, *Qh, *Kh, *Vpth, *Ah;
    float* bvp;
    cudaGetSymbolAddress((void**)&xh,   g_xh);
    cudaGetSymbolAddress((void**)&Wqh,  g_Wqh);
    cudaGetSymbolAddress((void**)&Wkh,  g_Wkh);
    cudaGetSymbolAddress((void**)&Wph,  g_Wph);
    cudaGetSymbolAddress((void**)&WvTh, g_WvTh);
    cudaGetSymbolAddress((void**)&Mh,   g_Mh);
    cudaGetSymbolAddress((void**)&bvp,  g_bvp);
    cudaGetSymbolAddress((void**)&Qh,   g_Qh);
    cudaGetSymbolAddress((void**)&Kh,   g_Kh);
    cudaGetSymbolAddress((void**)&Vpth, g_Vpth);
    cudaGetSymbolAddress((void**)&Ah,   g_Ah);

    static bool attr_set = false;
    if (!attr_set) {
        cudaFuncSetAttribute(hgemm_qkv,       cudaFuncAttributeMaxDynamicSharedMemorySize, SMEM_BYTES);
        cudaFuncSetAttribute(hgemm_kernel<0>, cudaFuncAttributeMaxDynamicSharedMemorySize, SMEM_BYTES);
        cudaFuncSetAttribute(hgemm_kernel<2>, cudaFuncAttributeMaxDynamicSharedMemorySize, SMEM_BYTES);
        attr_set = true;
    }

    const float inv_scale = (float)(1.0 / sqrt((double)DIM));

    // 0) conversions: x; Wq/Wk/Wp; WvT (transposed); bvp = Wp·bv + bp
    cvt_f2h<<<3072, 256>>>(x, xh, MROWS * DIM / 8);
    {
        dim3 grid(288, 3, 1);
        cvt_weights<<<grid, 256>>>(Wq, Wk, Wp, Wqh, Wkh, Wph, DIM * DIM / 8);
    }
    {
        dim3 grid(DIM / 32, DIM / 32, 1);
        cvt_transpose<<<grid, 256>>>(Wv, WvTh);
    }
    bvp_kernel<<<DIM / 128, 128>>>(Wp, bv, bp, bvp);

    // 0b) M = Wp @ Wv : C[f,d] = sum_k Wp[f,k] * WvT[d,k]  (fp16 out, 36 CTAs)
    {
        dim3 grid(DIM / BN, DIM / BM, 1);
        hgemm_kernel<0><<<grid, 128, SMEM_BYTES>>>(Wph, WvTh, nullptr, Mh,
                                                   DIM, DIM, 1.0f, 0, 0, 0);
    }

    // 1) Q/K/Vp projections in ONE launch: z<2 -> Qh/Kh; z=2 -> Vpt = (x@M^T)^T
    {
        dim3 grid(DIM / BN, MROWS / BM, 3);
        hgemm_qkv<<<grid, 128, SMEM_BYTES>>>(xh, Wqh, Wkh, Mh, bq, bk, Qh, Kh, Vpth);
    }

    // 2) scores: Ah[b,q,k] = (Q K^T) / sqrt(D)   (fp16 out)
    {
        dim3 grid(SEQ / BN, SEQ / BM, BATCH);
        hgemm_kernel<0><<<grid, 128, SMEM_BYTES>>>(Qh, Kh, nullptr, Ah,
                                                   SEQ, DIM, inv_scale,
                                                   (size_t)SEQ * DIM, (size_t)SEQ * DIM,
                                                   (size_t)SEQ * SEQ);
    }

    // 3) row softmax (fp16 in/out, fp32 math)
    softmax_h<<<BATCH * SEQ, 256>>>(Ah);

    // 4) out[b,q,f] = alpha[b,q,:] @ Vpt[b,f,:]^T + bvp[f]  (fp32 direct to d_out)
    {
        dim3 grid(DIM / BN, SEQ / BM, BATCH);
        hgemm_kernel<2><<<grid, 128, SMEM_BYTES>>>(Ah, Vpth, bvp, out,
                                                   DIM, SEQ, 1.0f,
                                                   (size_t)SEQ * SEQ, (size_t)DIM * SEQ,
                                                   (size_t)SEQ * DIM);
    }
}

// round 16
// speedup vs baseline: 1.1002x; 1.1002x over previous
#include <cuda_runtime.h>
#include <cuda_fp16.h>
#include <math.h>
#include <stdint.h>

// Problem constants
#define BATCH 8
#define SEQ   2048
#define DIM   768
#define MROWS (BATCH * SEQ)   // 16384

// GEMM tiling: CTA 128x128, 4 warps (2x2), warp tile 64x64  (R7 config, frozen)
#define BM 128
#define BN 128
#define BKH 32                 // k-chunk in halves
#define STAGES 3
#define ROWB 80                // smem bytes per row: 64B data + 16B pad
#define TILEB (128 * ROWB)     // 10240 B per operand tile
#define STAGEB (2 * TILEB)
#define SMEM_BYTES (STAGES * STAGEB)   // 61440  (x2 CTAs = 120KB <= 227KB)

// ---------------------------------------------------------------------------
// Scratch (allocation-free contract: __device__ globals)
// ---------------------------------------------------------------------------
__device__ __half g_xh  [(size_t)MROWS * DIM];
__device__ __half g_Wqh [DIM * DIM];
__device__ __half g_Wkh [DIM * DIM];
__device__ __half g_Wph [DIM * DIM];
__device__ __half g_WvTh[DIM * DIM];                  // Wv transposed, fp16
__device__ __half g_Mh  [DIM * DIM];                  // M = Wp @ Wv, fp16
__device__ float  g_bvp [DIM];                        // bvp = Wp·bv + bp
__device__ __half g_Qh  [(size_t)MROWS * DIM];
__device__ __half g_Kh  [(size_t)MROWS * DIM];
__device__ __half g_Vpth[(size_t)BATCH * DIM * SEQ];  // Vp^T: [b][f][s]
__device__ __half g_Ah  [(size_t)BATCH * SEQ * SEQ];  // attention matrix

// ---------------------------------------------------------------------------
// Helpers
// ---------------------------------------------------------------------------
__device__ __forceinline__ uint32_t smem_u32(const void* p) {
    uint32_t a;
    asm("{ .reg .u64 t; cvta.to.shared.u64 t, %1; cvt.u32.u64 %0, t; }" : "=r"(a) : "l"(p));
    return a;
}

__device__ __forceinline__ void cpasync16(uint32_t dst, const void* src) {
    asm volatile("cp.async.cg.shared.global [%0], [%1], 16;" :: "r"(dst), "l"(src) : "memory");
}

__device__ __forceinline__ void ldm_x4(uint32_t* r, uint32_t addr) {
    asm volatile("ldmatrix.sync.aligned.m8n8.x4.shared.b16 {%0,%1,%2,%3}, [%4];"
                 : "=r"(r[0]), "=r"(r[1]), "=r"(r[2]), "=r"(r[3]) : "r"(addr));
}

__device__ __forceinline__ void mma_f16(float* d, const uint32_t* a, const uint32_t* b) {
    asm volatile(
        "mma.sync.aligned.m16n8k16.row.col.f32.f16.f16.f32 "
        "{%0,%1,%2,%3}, {%4,%5,%6,%7}, {%8,%9}, {%0,%1,%2,%3};"
        : "+f"(d[0]), "+f"(d[1]), "+f"(d[2]), "+f"(d[3])
        : "r"(a[0]), "r"(a[1]), "r"(a[2]), "r"(a[3]), "r"(b[0]), "r"(b[1]));
}

// ---------------------------------------------------------------------------
// fp32 -> fp16 converters
// ---------------------------------------------------------------------------
__global__ void __launch_bounds__(256) cvt_f2h(const float* __restrict__ in,
                                               __half* __restrict__ out, int n8)
{
    for (int i = blockIdx.x * blockDim.x + threadIdx.x; i < n8; i += gridDim.x * blockDim.x) {
        float4 v0 = reinterpret_cast<const float4*>(in)[2 * i];
        float4 v1 = reinterpret_cast<const float4*>(in)[2 * i + 1];
        uint4 o;
        __half2 h;
        h = __floats2half2_rn(v0.x, v0.y); o.x = *reinterpret_cast<uint32_t*>(&h);
        h = __floats2half2_rn(v0.z, v0.w); o.y = *reinterpret_cast<uint32_t*>(&h);
        h = __floats2half2_rn(v1.x, v1.y); o.z = *reinterpret_cast<uint32_t*>(&h);
        h = __floats2half2_rn(v1.z, v1.w); o.w = *reinterpret_cast<uint32_t*>(&h);
        reinterpret_cast<uint4*>(out)[i] = o;
    }
}

// 3 weights (Wq, Wk, Wp) in one launch: blockIdx.y selects the matrix.
__global__ void __launch_bounds__(256) cvt_weights(
    const float* __restrict__ w0, const float* __restrict__ w1,
    const float* __restrict__ w2,
    __half* __restrict__ o0, __half* __restrict__ o1,
    __half* __restrict__ o2, int n8)
{
    const float* in  = (blockIdx.y == 0) ? w0 : (blockIdx.y == 1) ? w1 : w2;
    __half*      out = (blockIdx.y == 0) ? o0 : (blockIdx.y == 1) ? o1 : o2;
    for (int i = blockIdx.x * blockDim.x + threadIdx.x; i < n8; i += gridDim.x * blockDim.x) {
        float4 v0 = reinterpret_cast<const float4*>(in)[2 * i];
        float4 v1 = reinterpret_cast<const float4*>(in)[2 * i + 1];
        uint4 o;
        __half2 h;
        h = __floats2half2_rn(v0.x, v0.y); o.x = *reinterpret_cast<uint32_t*>(&h);
        h = __floats2half2_rn(v0.z, v0.w); o.y = *reinterpret_cast<uint32_t*>(&h);
        h = __floats2half2_rn(v1.x, v1.y); o.z = *reinterpret_cast<uint32_t*>(&h);
        h = __floats2half2_rn(v1.z, v1.w); o.w = *reinterpret_cast<uint32_t*>(&h);
        reinterpret_cast<uint4*>(out)[i] = o;
    }
}

// Transpose-convert: WvT[d,k] = (half)Wv[k,d]. 32x32 smem tiles.
__global__ void __launch_bounds__(256) cvt_transpose(const float* __restrict__ in,
                                                     __half* __restrict__ out)
{
    __shared__ float tile[32][33];
    const int bx = blockIdx.x * 32;   // k base
    const int by = blockIdx.y * 32;   // d base
    const int tx = threadIdx.x & 31;
    const int ty = threadIdx.x >> 5;  // 0..7
    #pragma unroll
    for (int i = 0; i < 4; i++) {
        int k = bx + ty + i * 8;
        tile[ty + i * 8][tx] = in[(size_t)k * DIM + by + tx];
    }
    __syncthreads();
    #pragma unroll
    for (int i = 0; i < 4; i++) {
        int d = by + ty + i * 8;
        out[(size_t)d * DIM + bx + tx] = __float2half_rn(tile[tx][ty + i * 8]);
    }
}

// bvp[f] = bp[f] + sum_k Wp[f,k] * bv[k]
// One warp per output f: lane-strided loads + shfl reduction.
// grid = DIM/8 blocks x 256 threads (8 warps) -> 768 warps total.
__global__ void __launch_bounds__(256) bvp_kernel(const float* __restrict__ Wp,
                                                  const float* __restrict__ bv,
                                                  const float* __restrict__ bp,
                                                  float* __restrict__ bvp)
{
    const int warp = threadIdx.x >> 5;
    const int lane = threadIdx.x & 31;
    const int f = blockIdx.x * 8 + warp;
    const float* row = Wp + (size_t)f * DIM;
    float s = 0.0f;
    #pragma unroll
    for (int k = lane; k < DIM; k += 32)
        s += row[k] * bv[k];
    #pragma unroll
    for (int o = 16; o > 0; o >>= 1)
        s += __shfl_xor_sync(0xffffffffu, s, o);
    if (lane == 0) bvp[f] = s + bp[f];
}

// ===========================================================================
// Shared mainloop (R7 config, frozen): 128x128 CTA tile of A @ B^T into acc.
// ===========================================================================
__device__ __forceinline__ void hgemm_mainloop(
    const __half* __restrict__ Ab, const __half* __restrict__ Bb,
    int K, uint32_t sbase, int tid, int lane, int warpM, int warpN,
    float acc[4][8][4])
{
    const int r0 = tid >> 2;       // 0..31
    const int kc = tid & 3;        // 0..3

    const int nc = K / BKH;

    auto prefetch = [&](int c) {
        const int s = c % STAGES;
        if (c < nc) {
            const __half* ap = Ab + (size_t)r0 * K + c * BKH + kc * 8;
            const __half* bp = Bb + (size_t)r0 * K + c * BKH + kc * 8;
            const uint32_t da = sbase + s * STAGEB + r0 * ROWB + kc * 16;
            const uint32_t db = da + TILEB;
            #pragma unroll
            for (int rr = 0; rr < 4; rr++) {
                cpasync16(da + rr * 32 * ROWB, ap + (size_t)(rr * 32) * K);
                cpasync16(db + rr * 32 * ROWB, bp + (size_t)(rr * 32) * K);
            }
        }
        asm volatile("cp.async.commit_group;" ::: "memory");
    };

    prefetch(0);
    prefetch(1);

    for (int c = 0; c < nc; c++) {
        asm volatile("cp.async.wait_group %0;" :: "n"(STAGES - 2) : "memory");
        __syncthreads();

        const int s = c % STAGES;
        const uint32_t sa = sbase + s * STAGEB;
        const uint32_t sb = sa + TILEB;

        #pragma unroll
        for (int kt = 0; kt < 2; kt++) {
            uint32_t af[4][4], bf[8][2];
            #pragma unroll
            for (int mt = 0; mt < 4; mt++) {
                const int m = warpM * 64 + mt * 16 + (lane & 15);
                const int k = kt * 16 + 8 * (lane >> 4);
                ldm_x4(af[mt], sa + m * ROWB + k * 2);
            }
            #pragma unroll
            for (int nb = 0; nb < 4; nb++) {
                const int n = warpN * 64 + nb * 16 + (lane & 7) + 8 * (lane >> 4);
                const int k = kt * 16 + 8 * ((lane >> 3) & 1);
                uint32_t r[4];
                ldm_x4(r, sb + n * ROWB + k * 2);
                bf[nb * 2][0]     = r[0]; bf[nb * 2][1]     = r[1];
                bf[nb * 2 + 1][0] = r[2]; bf[nb * 2 + 1][1] = r[3];
            }
            #pragma unroll
            for (int mt = 0; mt < 4; mt++)
                #pragma unroll
                for (int nt = 0; nt < 8; nt++)
                    mma_f16(acc[mt][nt], af[mt], bf[nt]);
        }
        prefetch(c + 2);
    }
    asm volatile("cp.async.wait_group 0;" ::: "memory");
}

// ---------------------------------------------------------------------------
// Merged Q/K/Vp projection: grid (6, 128, 3); z selects weight/output.
// z<2 -> Qh/Kh row-major (+bias); z=2 -> Vp = x@M^T, transposed Vpt store
// (NO bias: folded into bvp).
// ---------------------------------------------------------------------------
__global__ void __launch_bounds__(128, 2) hgemm_qkv(
    const __half* __restrict__ xh,
    const __half* __restrict__ Wq, const __half* __restrict__ Wk, const __half* __restrict__ M,
    const float* __restrict__ bq, const float* __restrict__ bk,
    __half* __restrict__ Qh, __half* __restrict__ Kh, __half* __restrict__ Vpth)
{
    extern __shared__ __align__(16) char smem[];
    const uint32_t sbase = smem_u32(smem);
    const int tid  = threadIdx.x;
    const int lane = tid & 31;
    const int wid  = tid >> 5;
    const int warpM = wid & 1;
    const int warpN = wid >> 1;
    const int bx = blockIdx.x, by = blockIdx.y, bz = blockIdx.z;

    const __half* W    = (bz == 0) ? Wq : (bz == 1) ? Wk : M;
    const float*  bias = (bz == 0) ? bq : (bz == 1) ? bk : nullptr;

    const __half* Ab = xh + (size_t)(by * BM) * DIM;
    const __half* Bb = W  + (size_t)(bx * BN) * DIM;

    float acc[4][8][4];
    #pragma unroll
    for (int i = 0; i < 4; i++)
        #pragma unroll
        for (int j = 0; j < 8; j++)
            #pragma unroll
            for (int q = 0; q < 4; q++) acc[i][j][q] = 0.0f;

    hgemm_mainloop(Ab, Bb, DIM, sbase, tid, lane, warpM, warpN, acc);

    const int rbase = lane >> 2;
    const int cbase = 2 * (lane & 3);

    if (bz < 2) {
        __half* Cb = (bz == 0 ? Qh : Kh) + (size_t)(by * BM) * DIM + bx * BN;
        #pragma unroll
        for (int mt = 0; mt < 4; mt++) {
            #pragma unroll
            for (int nt = 0; nt < 8; nt++) {
                const int col = warpN * 64 + nt * 8 + cbase;
                const float b0 = bias[bx * BN + col];
                const float b1 = bias[bx * BN + col + 1];
                #pragma unroll
                for (int h = 0; h < 2; h++) {
                    const int row = warpM * 64 + mt * 16 + rbase + 8 * h;
                    *reinterpret_cast<__half2*>(Cb + (size_t)row * DIM + col) =
                        __floats2half2_rn(acc[mt][nt][2 * h + 0] + b0,
                                          acc[mt][nt][2 * h + 1] + b1);
                }
            }
        }
    } else {
        // transposed store into Vpt[b][f][s] via smem staging (no bias)
        __syncthreads();
        __half* Ts = reinterpret_cast<__half*>(smem);   // [128 f][136 m-halves]
        #pragma unroll
        for (int mt = 0; mt < 4; mt++) {
            #pragma unroll
            for (int nt = 0; nt < 8; nt++) {
                const int col = warpN * 64 + nt * 8 + cbase;
                #pragma unroll
                for (int h = 0; h < 2; h++) {
                    const int row = warpM * 64 + mt * 16 + rbase + 8 * h;
                    Ts[(col)     * 136 + row] = __float2half_rn(acc[mt][nt][2 * h + 0]);
                    Ts[(col + 1) * 136 + row] = __float2half_rn(acc[mt][nt][2 * h + 1]);
                }
            }
        }
        __syncthreads();
        const int mglob = by * BM;
        const int bb = mglob / SEQ;
        const int s0 = mglob % SEQ;
        __half* Ob = Vpth + ((size_t)bb * DIM + bx * BN) * SEQ + s0;
        const int d = tid;
        const uint4* src = reinterpret_cast<const uint4*>(Ts + d * 136);
        uint4* dst = reinterpret_cast<uint4*>(Ob + (size_t)d * SEQ);
        #pragma unroll
        for (int i = 0; i < 16; i++) dst[i] = src[i];
    }
}

// ---------------------------------------------------------------------------
// General GEMM (R7): OUTMODE 0 fp16 row-major; OUTMODE 2 fp32 row-major.
// ---------------------------------------------------------------------------
template<int OUTMODE>
__global__ void __launch_bounds__(128, 2) hgemm_kernel(
    const __half* __restrict__ A, const __half* __restrict__ B,
    const float* __restrict__ bias, void* __restrict__ Cv,
    int ldC, int K, float scale,
    size_t strideA, size_t strideB, size_t strideC)
{
    extern __shared__ __align__(16) char smem[];
    const uint32_t sbase = smem_u32(smem);
    const int tid  = threadIdx.x;
    const int lane = tid & 31;
    const int wid  = tid >> 5;
    const int warpM = wid & 1;
    const int warpN = wid >> 1;
    const int bx = blockIdx.x, by = blockIdx.y, bz = blockIdx.z;

    const __half* Ab = A + bz * strideA + (size_t)(by * BM) * K;
    const __half* Bb = B + bz * strideB + (size_t)(bx * BN) * K;

    float acc[4][8][4];
    #pragma unroll
    for (int i = 0; i < 4; i++)
        #pragma unroll
        for (int j = 0; j < 8; j++)
            #pragma unroll
            for (int q = 0; q < 4; q++) acc[i][j][q] = 0.0f;

    hgemm_mainloop(Ab, Bb, K, sbase, tid, lane, warpM, warpN, acc);

    const int rbase = lane >> 2;
    const int cbase = 2 * (lane & 3);

    #pragma unroll
    for (int mt = 0; mt < 4; mt++) {
        #pragma unroll
        for (int nt = 0; nt < 8; nt++) {
            const int col = warpN * 64 + nt * 8 + cbase;
            const float b0 = bias ? bias[bx * BN + col]     : 0.0f;
            const float b1 = bias ? bias[bx * BN + col + 1] : 0.0f;
            #pragma unroll
            for (int h = 0; h < 2; h++) {
                const int row = warpM * 64 + mt * 16 + rbase + 8 * h;
                const float v0 = acc[mt][nt][2 * h + 0] * scale + b0;
                const float v1 = acc[mt][nt][2 * h + 1] * scale + b1;
                if (OUTMODE == 0) {
                    __half* Cb = (__half*)Cv + bz * strideC + (size_t)(by * BM) * ldC + bx * BN;
                    *reinterpret_cast<__half2*>(Cb + (size_t)row * ldC + col) =
                        __floats2half2_rn(v0, v1);
                } else {
                    float* Cb = (float*)Cv + bz * strideC + (size_t)(by * BM) * ldC + bx * BN;
                    *reinterpret_cast<float2*>(Cb + (size_t)row * ldC + col) =
                        make_float2(v0, v1);
                }
            }
        }
    }
}

// ---------------------------------------------------------------------------
// Row softmax over SEQ=2048 fp16 elements: one block (256 threads) per row.
// ---------------------------------------------------------------------------
__global__ void __launch_bounds__(256) softmax_h(__half* __restrict__ alpha)
{
    __shared__ float redmax[8];
    __shared__ float redsum[8];

    __half* row = alpha + (size_t)blockIdx.x * SEQ;
    const int tid = threadIdx.x;

    uint4 u = reinterpret_cast<uint4*>(row)[tid];     // 8 halves
    __half2* hp = reinterpret_cast<__half2*>(&u);
    float v[8];
    #pragma unroll
    for (int i = 0; i < 4; i++) {
        float2 f = __half22float2(hp[i]);
        v[2 * i] = f.x; v[2 * i + 1] = f.y;
    }

    float m = v[0];
    #pragma unroll
    for (int i = 1; i < 8; i++) m = fmaxf(m, v[i]);
    #pragma unroll
    for (int o = 16; o > 0; o >>= 1) m = fmaxf(m, __shfl_xor_sync(0xffffffffu, m, o));
    if ((tid & 31) == 0) redmax[tid >> 5] = m;
    __syncthreads();
    if (tid < 32) {
        float t = (tid < 8) ? redmax[tid] : -INFINITY;
        #pragma unroll
        for (int o = 4; o > 0; o >>= 1) t = fmaxf(t, __shfl_xor_sync(0xffffffffu, t, o));
        if (tid == 0) redmax[0] = t;
    }
    __syncthreads();
    m = redmax[0];

    float s = 0.0f;
    #pragma unroll
    for (int i = 0; i < 8; i++) { v[i] = __expf(v[i] - m); s += v[i]; }
    #pragma unroll
    for (int o = 16; o > 0; o >>= 1) s += __shfl_xor_sync(0xffffffffu, s, o);
    if ((tid & 31) == 0) redsum[tid >> 5] = s;
    __syncthreads();
    if (tid < 32) {
        float t = (tid < 8) ? redsum[tid] : 0.0f;
        #pragma unroll
        for (int o = 4; o > 0; o >>= 1) t += __shfl_xor_sync(0xffffffffu, t, o);
        if (tid == 0) redsum[0] = t;
    }
    __syncthreads();
    const float inv = 1.0f / redsum[0];

    #pragma unroll
    for (int i = 0; i < 4; i++)
        hp[i] = __floats2half2_rn(v[2 * i] * inv, v[2 * i + 1] * inv);
    reinterpret_cast<uint4*>(row)[tid] = u;
}

// ---------------------------------------------------------------------------
// kernel_launch
// ---------------------------------------------------------------------------
extern "C" void kernel_launch(void* const* d_in, const int* in_sizes, int n_in,
                              void* d_out, int out_size)
{
    (void)in_sizes; (void)n_in; (void)out_size;

    const float* x  = (const float*)d_in[0];
    const float* Wq = (const float*)d_in[1];
    const float* bq = (const float*)d_in[2];
    const float* Wk = (const float*)d_in[3];
    const float* bk = (const float*)d_in[4];
    const float* Wv = (const float*)d_in[5];
    const float* bv = (const float*)d_in[6];
    const float* Wp = (const float*)d_in[7];
    const float* bp = (const float*)d_in[8];
    float* out = (float*)d_out;

    __half *xh, *Wqh, *Wkh, *Wph, *WvTh, *Mh, *Qh, *Kh, *Vpth, *Ah;
    float* bvp;
    cudaGetSymbolAddress((void**)&xh,   g_xh);
    cudaGetSymbolAddress((void**)&Wqh,  g_Wqh);
    cudaGetSymbolAddress((void**)&Wkh,  g_Wkh);
    cudaGetSymbolAddress((void**)&Wph,  g_Wph);
    cudaGetSymbolAddress((void**)&WvTh, g_WvTh);
    cudaGetSymbolAddress((void**)&Mh,   g_Mh);
    cudaGetSymbolAddress((void**)&bvp,  g_bvp);
    cudaGetSymbolAddress((void**)&Qh,   g_Qh);
    cudaGetSymbolAddress((void**)&Kh,   g_Kh);
    cudaGetSymbolAddress((void**)&Vpth, g_Vpth);
    cudaGetSymbolAddress((void**)&Ah,   g_Ah);

    static bool attr_set = false;
    if (!attr_set) {
        cudaFuncSetAttribute(hgemm_qkv,       cudaFuncAttributeMaxDynamicSharedMemorySize, SMEM_BYTES);
        cudaFuncSetAttribute(hgemm_kernel<0>, cudaFuncAttributeMaxDynamicSharedMemorySize, SMEM_BYTES);
        cudaFuncSetAttribute(hgemm_kernel<2>, cudaFuncAttributeMaxDynamicSharedMemorySize, SMEM_BYTES);
        attr_set = true;
    }

    const float inv_scale = (float)(1.0 / sqrt((double)DIM));

    // 0) conversions: x; Wq/Wk/Wp; WvT (transposed); bvp = Wp·bv + bp
    cvt_f2h<<<3072, 256>>>(x, xh, MROWS * DIM / 8);
    {
        dim3 grid(288, 3, 1);
        cvt_weights<<<grid, 256>>>(Wq, Wk, Wp, Wqh, Wkh, Wph, DIM * DIM / 8);
    }
    {
        dim3 grid(DIM / 32, DIM / 32, 1);
        cvt_transpose<<<grid, 256>>>(Wv, WvTh);
    }
    bvp_kernel<<<DIM / 8, 256>>>(Wp, bv, bp, bvp);

    // 0b) M = Wp @ Wv : C[f,d] = sum_k Wp[f,k] * WvT[d,k]  (fp16 out, 36 CTAs)
    {
        dim3 grid(DIM / BN, DIM / BM, 1);
        hgemm_kernel<0><<<grid, 128, SMEM_BYTES>>>(Wph, WvTh, nullptr, Mh,
                                                   DIM, DIM, 1.0f, 0, 0, 0);
    }

    // 1) Q/K/Vp projections in ONE launch: z<2 -> Qh/Kh; z=2 -> Vpt = (x@M^T)^T
    {
        dim3 grid(DIM / BN, MROWS / BM, 3);
        hgemm_qkv<<<grid, 128, SMEM_BYTES>>>(xh, Wqh, Wkh, Mh, bq, bk, Qh, Kh, Vpth);
    }

    // 2) scores: Ah[b,q,k] = (Q K^T) / sqrt(D)   (fp16 out)
    {
        dim3 grid(SEQ / BN, SEQ / BM, BATCH);
        hgemm_kernel<0><<<grid, 128, SMEM_BYTES>>>(Qh, Kh, nullptr, Ah,
                                                   SEQ, DIM, inv_scale,
                                                   (size_t)SEQ * DIM, (size_t)SEQ * DIM,
                                                   (size_t)SEQ * SEQ);
    }

    // 3) row softmax (fp16 in/out, fp32 math)
    softmax_h<<<BATCH * SEQ, 256>>>(Ah);

    // 4) out[b,q,f] = alpha[b,q,:] @ Vpt[b,f,:]^T + bvp[f]  (fp32 direct to d_out)
    {
        dim3 grid(DIM / BN, SEQ / BM, BATCH);
        hgemm_kernel<2><<<grid, 128, SMEM_BYTES>>>(Ah, Vpth, bvp, out,
                                                   DIM, SEQ, 1.0f,
                                                   (size_t)SEQ * SEQ, (size_t)DIM * SEQ,
                                                   (size_t)SEQ * DIM);
    }
}